// round 5
// baseline (speedup 1.0000x reference)
#include <cuda_runtime.h>
#include <cstddef>

// out[t, e] = cos(t) * rowsum(W[e,:]) + b[e]
// T = 65536, E = 1024. Pure store-bound: 256 MB fp32 output, one pass.
// x (the 2M-element input) is mathematically unused and never read.
//
// R4 -> R5 changes:
//   * __stcs streaming stores: output is write-once/read-never inside this
//     kernel; evict-first policy keeps the 256MB stream from thrashing L2.
//   * ROWS 32 -> 16 (grid 2048 -> 4096): smaller blocks, ~3.5 waves instead
//     of 1.73 -> much smaller partial-wave tail on 148 SMs.

#define EDIM      1024
#define THREADS   256          // one float4 (4 e-values) per thread per row
#define ROWS      16           // t-rows per block

__global__ __launch_bounds__(THREADS, 8)
void pe_quantum_kernel(const float* __restrict__ W,   // [E, 8]
                       const float* __restrict__ b,   // [E]
                       float4* __restrict__ out,      // [T, E/4] as float4
                       int T)
{
    const int i = threadIdx.x;             // 0..255 -> e block [4i, 4i+4)
    const int t0 = blockIdx.x * ROWS;

    // --- per-thread constants: a_k = sum_q W[4i+k, q], held in registers ---
    const float4* W4 = reinterpret_cast<const float4*>(W) + (size_t)i * 8;
    float a0, a1, a2, a3;
    {
        float4 w0 = W4[0], w1 = W4[1];     // row e=4i
        float4 w2 = W4[2], w3 = W4[3];     // row e=4i+1
        float4 w4 = W4[4], w5 = W4[5];     // row e=4i+2
        float4 w6 = W4[6], w7 = W4[7];     // row e=4i+3
        a0 = (w0.x + w0.y) + (w0.z + w0.w) + (w1.x + w1.y) + (w1.z + w1.w);
        a1 = (w2.x + w2.y) + (w2.z + w2.w) + (w3.x + w3.y) + (w3.z + w3.w);
        a2 = (w4.x + w4.y) + (w4.z + w4.w) + (w5.x + w5.y) + (w5.z + w5.w);
        a3 = (w6.x + w6.y) + (w6.z + w6.w) + (w7.x + w7.y) + (w7.z + w7.w);
    }
    const float4 bb = reinterpret_cast<const float4*>(b)[i];

    // --- cos(t) once per row, shared across the block ---
    __shared__ float cost[ROWS];
    if (i < ROWS) {
        int t = t0 + i;
        cost[i] = (t < T) ? cosf((float)t) : 0.0f;   // accurate range reduction
    }
    __syncthreads();

    // --- ROWS coalesced streaming STG.128 per thread ---
    float4* dst = out + (size_t)t0 * (EDIM / 4) + i;
    #pragma unroll
    for (int r = 0; r < ROWS; ++r) {
        int t = t0 + r;
        if (t >= T) break;
        const float c = cost[r];
        float4 v;
        v.x = fmaf(c, a0, bb.x);
        v.y = fmaf(c, a1, bb.y);
        v.z = fmaf(c, a2, bb.z);
        v.w = fmaf(c, a3, bb.w);
        __stcs(dst, v);                    // streaming: evict-first in L2
        dst += EDIM / 4;
    }
}

extern "C" void kernel_launch(void* const* d_in, const int* in_sizes, int n_in,
                              void* d_out, int out_size)
{
    // Identify W (E*8 = 8192 elems) and b (E = 1024 elems) by size; x unused.
    const float* W = nullptr;
    const float* b = nullptr;
    for (int k = 0; k < n_in; ++k) {
        if (in_sizes[k] == EDIM * 8)      W = (const float*)d_in[k];
        else if (in_sizes[k] == EDIM)     b = (const float*)d_in[k];
    }
    if (!W && n_in >= 2) W = (const float*)d_in[1];
    if (!b && n_in >= 3) b = (const float*)d_in[2];

    const int T = out_size / EDIM;                 // 65536
    const int grid = (T + ROWS - 1) / ROWS;        // 4096 blocks

    pe_quantum_kernel<<<grid, THREADS>>>(W, b, (float4*)d_out, T);
}

// round 6
// speedup vs baseline: 1.2165x; 1.2165x over previous
#include <cuda_runtime.h>
#include <cstdint>
#include <cstddef>

// out[t, e] = cos(t) * rowsum(W[e,:]) + b[e]
// T = 65536, E = 1024. Pure store-bound: 256 MB fp32 output, one pass.
// x (the 2M-element input) is mathematically unused and never read.
//
// R5 -> R6: replace per-thread STG.128 with SMEM-staged 1-D TMA bulk stores
// (cp.async.bulk.global.shared::cta.bulk_group). Persistent grid, double-
// buffered 32KB tiles, 3 blocks/SM. The TMA engine writes full 128B lines
// sequentially and sustains the LTS cap; the SM only does cheap STS + FMA.

#define EDIM        1024
#define THREADS     256
#define TROWS       8                          // t-rows per tile
#define TILE_FLOATS (TROWS * EDIM)             // 8192 floats
#define TILE_BYTES  (TILE_FLOATS * 4)          // 32 KB
#define NBUF        2

__device__ __forceinline__ uint32_t smem_u32(const void* p) {
    uint32_t a;
    asm("{ .reg .u64 t; cvta.to.shared.u64 t, %1; cvt.u32.u64 %0, t; }"
        : "=r"(a) : "l"(p));
    return a;
}

extern __shared__ float sbuf[];                // NBUF * TILE_FLOATS

__global__ __launch_bounds__(THREADS)
void pe_tma_kernel(const float* __restrict__ W,   // [E, 8]
                   const float* __restrict__ b,   // [E]
                   float* __restrict__ out,       // [T, E]
                   int T)
{
    const int i = threadIdx.x;                 // 0..255 -> e block [4i, 4i+4)

    // --- per-thread constants: a_k = sum_q W[4i+k, q] (registers, loaded once) ---
    const float4* W4 = reinterpret_cast<const float4*>(W) + (size_t)i * 8;
    float a0, a1, a2, a3;
    {
        float4 w0 = W4[0], w1 = W4[1];
        float4 w2 = W4[2], w3 = W4[3];
        float4 w4 = W4[4], w5 = W4[5];
        float4 w6 = W4[6], w7 = W4[7];
        a0 = (w0.x + w0.y) + (w0.z + w0.w) + (w1.x + w1.y) + (w1.z + w1.w);
        a1 = (w2.x + w2.y) + (w2.z + w2.w) + (w3.x + w3.y) + (w3.z + w3.w);
        a2 = (w4.x + w4.y) + (w4.z + w4.w) + (w5.x + w5.y) + (w5.z + w5.w);
        a3 = (w6.x + w6.y) + (w6.z + w6.w) + (w7.x + w7.y) + (w7.z + w7.w);
    }
    const float4 bb = reinterpret_cast<const float4*>(b)[i];

    __shared__ float cost[TROWS];

    const int ntiles = T / TROWS;              // 8192
    int iter = 0;
    for (int tile = blockIdx.x; tile < ntiles; tile += gridDim.x, ++iter) {
        const int p = iter & 1;
        float4* buf4 = reinterpret_cast<float4*>(sbuf + p * TILE_FLOATS);
        const int t0 = tile * TROWS;

        // Free the buffer we are about to overwrite: allow at most 1 pending
        // bulk-store group whose SMEM reads are unfinished (the other buffer).
        if (i == 0 && iter >= NBUF)
            asm volatile("cp.async.bulk.wait_group.read 1;" ::: "memory");

        if (i < TROWS)
            cost[i] = cosf((float)(t0 + i));   // accurate range reduction
        __syncthreads();                       // orders wait + cost before writes

        #pragma unroll
        for (int r = 0; r < TROWS; ++r) {
            const float c = cost[r];
            float4 v;
            v.x = fmaf(c, a0, bb.x);
            v.y = fmaf(c, a1, bb.y);
            v.z = fmaf(c, a2, bb.z);
            v.w = fmaf(c, a3, bb.w);
            buf4[r * (EDIM / 4) + i] = v;      // STS.128, conflict-free
        }

        // Make generic-proxy SMEM writes visible to the async (TMA) proxy.
        asm volatile("fence.proxy.async.shared::cta;" ::: "memory");
        __syncthreads();

        if (i == 0) {
            const uint32_t s = smem_u32(buf4);
            float* g = out + (size_t)t0 * EDIM;
            asm volatile(
                "cp.async.bulk.global.shared::cta.bulk_group [%0], [%1], %2;"
                :: "l"(g), "r"(s), "n"(TILE_BYTES) : "memory");
            asm volatile("cp.async.bulk.commit_group;" ::: "memory");
        }
    }

    // Drain all outstanding bulk stores before kernel exit.
    if (i == 0)
        asm volatile("cp.async.bulk.wait_group 0;" ::: "memory");
}

extern "C" void kernel_launch(void* const* d_in, const int* in_sizes, int n_in,
                              void* d_out, int out_size)
{
    // Identify W (E*8 elems) and b (E elems) by size; x is unused.
    const float* W = nullptr;
    const float* b = nullptr;
    for (int k = 0; k < n_in; ++k) {
        if (in_sizes[k] == EDIM * 8)      W = (const float*)d_in[k];
        else if (in_sizes[k] == EDIM)     b = (const float*)d_in[k];
    }
    if (!W && n_in >= 2) W = (const float*)d_in[1];
    if (!b && n_in >= 3) b = (const float*)d_in[2];

    const int T = out_size / EDIM;             // 65536

    static bool attr_set = false;
    if (!attr_set) {
        cudaFuncSetAttribute(pe_tma_kernel,
                             cudaFuncAttributeMaxDynamicSharedMemorySize,
                             NBUF * TILE_BYTES);
        attr_set = true;
    }

    const int grid = 148 * 3;                  // persistent: 3 blocks/SM (64KB smem each)
    pe_tma_kernel<<<grid, THREADS, NBUF * TILE_BYTES>>>(W, b, (float*)d_out, T);
}